// round 4
// baseline (speedup 1.0000x reference)
#include <cuda_runtime.h>
#include <cuda_bf16.h>
#include <cstdint>

#define N_NODES 50000
#define N_EDGES 800000
#define D 128
#define R 4
#define NSEG (N_NODES * R)      // 200000
#define NLAYER 3
#define KTOT 640                // R*D + D
#define MPAD 50048              // 391 * 128
#define NTILES 391
#define NCHUNK 10               // K chunks of 64 bf16 (128B rows)

// ---------------- static device scratch ----------------
__device__ __align__(16) __nv_bfloat16 g_ah[(size_t)MPAD * KTOT];  // A hi  [node][640]
__device__ __align__(16) __nv_bfloat16 g_al[(size_t)MPAD * KTOT];  // A lo
__device__ __align__(16) __nv_bfloat16 g_bh[(size_t)NLAYER * D * KTOT]; // B hi [l][n][k]
__device__ __align__(16) __nv_bfloat16 g_bl[(size_t)NLAYER * D * KTOT]; // B lo
__device__ float g_x1[(size_t)N_NODES * D];
__device__ float g_x2[(size_t)N_NODES * D];
__device__ int   g_cnt[NSEG];
__device__ int   g_off[NSEG + 1];
__device__ int   g_cursor[NSEG];
__device__ int   g_bsum[256];
__device__ int   g_srcs[N_EDGES];

// ---------------- helpers ----------------
__device__ __forceinline__ uint32_t smem_to_u32(const void* p) {
    uint32_t a;
    asm("{ .reg .u64 t; cvta.to.shared.u64 t, %1; cvt.u32.u64 %0, t; }"
        : "=r"(a) : "l"(p));
    return a;
}

#define CP16(sm, gp) \
    asm volatile("cp.async.cg.shared.global [%0], [%1], 16;" :: "r"(sm), "l"(gp))

__device__ __forceinline__ void ldsm_x4(uint32_t* f, uint32_t addr) {
    asm volatile("ldmatrix.sync.aligned.m8n8.x4.shared.b16 {%0,%1,%2,%3}, [%4];"
                 : "=r"(f[0]), "=r"(f[1]), "=r"(f[2]), "=r"(f[3]) : "r"(addr));
}

__device__ __forceinline__ void mma16816(float* d, const uint32_t* a,
                                         uint32_t b0, uint32_t b1) {
    asm volatile(
        "mma.sync.aligned.m16n8k16.row.col.f32.bf16.bf16.f32 "
        "{%0,%1,%2,%3}, {%4,%5,%6,%7}, {%8,%9}, {%0,%1,%2,%3};"
        : "+f"(d[0]), "+f"(d[1]), "+f"(d[2]), "+f"(d[3])
        : "r"(a[0]), "r"(a[1]), "r"(a[2]), "r"(a[3]), "r"(b0), "r"(b1));
}

// ---------------- CSR build ----------------
__global__ void k_zero_cnt() {
    int i = blockIdx.x * blockDim.x + threadIdx.x;
    if (i < NSEG) g_cnt[i] = 0;
}

__global__ void k_hist(const int* __restrict__ dst, const int* __restrict__ et) {
    int e = blockIdx.x * blockDim.x + threadIdx.x;
    if (e < N_EDGES) atomicAdd(&g_cnt[dst[e] * R + et[e]], 1);
}

__global__ void k_scan1() {
    __shared__ int sh[1024];
    int t = threadIdx.x;
    int i = blockIdx.x * 1024 + t;
    int v = (i < NSEG) ? g_cnt[i] : 0;
    sh[t] = v;
    __syncthreads();
    for (int d = 1; d < 1024; d <<= 1) {
        int add = (t >= d) ? sh[t - d] : 0;
        __syncthreads();
        sh[t] += add;
        __syncthreads();
    }
    if (i < NSEG) g_off[i] = sh[t] - v;
    if (t == 1023) g_bsum[blockIdx.x] = sh[1023];
}

// fused scan2+scan3: every block redundantly scans the 196 block sums
__global__ void k_scan23(int nb) {
    __shared__ int sh[256];
    int t = threadIdx.x;
    if (t < 256) sh[t] = (t < nb) ? g_bsum[t] : 0;
    __syncthreads();
    for (int d = 1; d < 256; d <<= 1) {
        int add = 0;
        if (t < 256 && t >= d) add = sh[t - d];
        __syncthreads();
        if (t < 256) sh[t] += add;
        __syncthreads();
    }
    int boff = (blockIdx.x > 0) ? sh[blockIdx.x - 1] : 0;
    int i = blockIdx.x * 1024 + t;
    if (i < NSEG) {
        int o = g_off[i] + boff;
        g_off[i] = o;
        g_cursor[i] = o;
    }
    if (i == 0) g_off[NSEG] = N_EDGES;
}

__global__ void k_scatter(const int* __restrict__ src, const int* __restrict__ dst,
                          const int* __restrict__ et) {
    int e = blockIdx.x * blockDim.x + threadIdx.x;
    if (e < N_EDGES) {
        int seg = dst[e] * R + et[e];
        int pos = atomicAdd(&g_cursor[seg], 1);
        g_srcs[pos] = src[e];
    }
}

// ---------------- weight prep: transpose + bf16 split ----------------
__global__ void k_bprep(const float* __restrict__ W, const float* __restrict__ root) {
    int i = blockIdx.x * 256 + threadIdx.x;     // over NLAYER*D*KTOT
    if (i >= NLAYER * D * KTOT) return;
    int k = i % KTOT;
    int t = i / KTOT;
    int n = t % D;
    int l = t / D;
    float w;
    if (k < 512) {
        int r = k >> 7, din = k & 127;
        w = W[(((size_t)l * R + r) * D + din) * D + n];
    } else {
        w = root[((size_t)l * D + (k - 512)) * D + n];
    }
    __nv_bfloat16 h = __float2bfloat16(w);
    float lo = w - __bfloat162float(h);
    g_bh[i] = h;
    g_bl[i] = __float2bfloat16(lo);
}

// ---------------- fill self-columns (512..639) of A from fp32 activations ----------------
__global__ void k_convx(const float* __restrict__ x) {
    int row = blockIdx.x * 8 + (threadIdx.x >> 5);
    if (row >= N_NODES) return;
    int lane = threadIdx.x & 31;
    float4 v = *reinterpret_cast<const float4*>(x + (size_t)row * D + lane * 4);
    __nv_bfloat16 h[4], lo[4];
    float vv[4] = {v.x, v.y, v.z, v.w};
#pragma unroll
    for (int j = 0; j < 4; j++) {
        h[j] = __float2bfloat16(vv[j]);
        lo[j] = __float2bfloat16(vv[j] - __bfloat162float(h[j]));
    }
    size_t o = (size_t)row * KTOT + 512 + lane * 4;
    *reinterpret_cast<uint2*>(&g_ah[o]) = *reinterpret_cast<uint2*>(h);
    *reinterpret_cast<uint2*>(&g_al[o]) = *reinterpret_cast<uint2*>(lo);
}

// ---------------- aggregation: warp per NODE (4 relations at once) ----------------
__global__ void k_agg(const float* __restrict__ x) {
    int node = blockIdx.x * 8 + (threadIdx.x >> 5);
    if (node >= N_NODES) return;
    int lane = threadIdx.x & 31;
    int base = node * 4;
    int off_l = (lane < 5) ? g_off[base + lane] : 0;
    int b0 = __shfl_sync(0xFFFFFFFFu, off_l, 0);
    int b1 = __shfl_sync(0xFFFFFFFFu, off_l, 1);
    int b2 = __shfl_sync(0xFFFFFFFFu, off_l, 2);
    int b3 = __shfl_sync(0xFFFFFFFFu, off_l, 3);
    int b4 = __shfl_sync(0xFFFFFFFFu, off_l, 4);

    float acc[4][4];
#pragma unroll
    for (int r = 0; r < 4; r++)
#pragma unroll
        for (int j = 0; j < 4; j++) acc[r][j] = 0.f;

    for (int jb = b0; jb < b4; jb += 32) {
        int j = jb + lane;
        int sn = (j < b4) ? g_srcs[j] : 0;
        int cnt = min(b4 - jb, 32);
        for (int i = 0; i < cnt; i++) {
            int s = __shfl_sync(0xFFFFFFFFu, sn, i);
            float4 v = *reinterpret_cast<const float4*>(x + (size_t)s * D + lane * 4);
            int idx = jb + i;
            float m0 = (idx < b1) ? 1.f : 0.f;
            float m1 = (idx >= b1 && idx < b2) ? 1.f : 0.f;
            float m2 = (idx >= b2 && idx < b3) ? 1.f : 0.f;
            float m3 = (idx >= b3) ? 1.f : 0.f;
            acc[0][0] = fmaf(v.x, m0, acc[0][0]); acc[0][1] = fmaf(v.y, m0, acc[0][1]);
            acc[0][2] = fmaf(v.z, m0, acc[0][2]); acc[0][3] = fmaf(v.w, m0, acc[0][3]);
            acc[1][0] = fmaf(v.x, m1, acc[1][0]); acc[1][1] = fmaf(v.y, m1, acc[1][1]);
            acc[1][2] = fmaf(v.z, m1, acc[1][2]); acc[1][3] = fmaf(v.w, m1, acc[1][3]);
            acc[2][0] = fmaf(v.x, m2, acc[2][0]); acc[2][1] = fmaf(v.y, m2, acc[2][1]);
            acc[2][2] = fmaf(v.z, m2, acc[2][2]); acc[2][3] = fmaf(v.w, m2, acc[2][3]);
            acc[3][0] = fmaf(v.x, m3, acc[3][0]); acc[3][1] = fmaf(v.y, m3, acc[3][1]);
            acc[3][2] = fmaf(v.z, m3, acc[3][2]); acc[3][3] = fmaf(v.w, m3, acc[3][3]);
        }
    }

    int cnts[4] = {b1 - b0, b2 - b1, b3 - b2, b4 - b3};
#pragma unroll
    for (int r = 0; r < 4; r++) {
        float inv = (cnts[r] > 0) ? 1.0f / (float)cnts[r] : 0.0f;
        __nv_bfloat16 h[4], lo[4];
#pragma unroll
        for (int j = 0; j < 4; j++) {
            float vv = acc[r][j] * inv;
            h[j] = __float2bfloat16(vv);
            lo[j] = __float2bfloat16(vv - __bfloat162float(h[j]));
        }
        size_t o = (size_t)node * KTOT + r * 128 + lane * 4;
        *reinterpret_cast<uint2*>(&g_ah[o]) = *reinterpret_cast<uint2*>(h);
        *reinterpret_cast<uint2*>(&g_al[o]) = *reinterpret_cast<uint2*>(lo);
    }
}

// ---------------- HMMA GEMM + fused relu/residual/LayerNorm epilogue ----------------
// smem: [0:512) bias, tiles at 1024 + buf*65536: Ah(16K) Al(16K) Bh(16K) Bl(16K)
// epilogue reuses [1024, 1024+67584) as 128x132 f32 staging
#define SMEM_DYN (1024 + 2 * 65536)

__global__ void __launch_bounds__(256) k_gemm(int layer, const float* __restrict__ bias,
                                              const float* __restrict__ xin,
                                              const float* __restrict__ gamma,
                                              const float* __restrict__ beta,
                                              float* __restrict__ xout,
                                              int write_next) {
    extern __shared__ char smem[];
    float* sBias = (float*)smem;
    uint32_t smem_u = smem_to_u32(smem);
    int tid = threadIdx.x;
    int wid = tid >> 5;
    int lane = tid & 31;
    int brow = blockIdx.x * 128;

    if (tid < 32) {
        float4 b = *reinterpret_cast<const float4*>(bias + tid * 4);
        *reinterpret_cast<float4*>(&sBias[tid * 4]) = b;
    }

    const __nv_bfloat16* bh = g_bh + (size_t)layer * D * KTOT;
    const __nv_bfloat16* bl = g_bl + (size_t)layer * D * KTOT;

    // warp tile: 32 (m) x 64 (n)
    int wm = wid & 3;            // m0 = wm*32
    int wn = wid >> 2;           // n0 = wn*64
    int lrow = lane & 15;        // ldmatrix row within 16-row tile
    int kh16 = (lane >> 4) * 16; // k-half byte offset

    float acc[2][8][4];
#pragma unroll
    for (int t = 0; t < 2; t++)
#pragma unroll
        for (int q = 0; q < 8; q++)
#pragma unroll
            for (int j = 0; j < 4; j++) acc[t][q][j] = 0.f;

    auto load_chunk = [&](int c, int buf) {
        uint32_t base = smem_u + 1024 + buf * 65536;
        int kcol = c * 64;
#pragma unroll
        for (int it = 0; it < 4; it++) {
            int u = tid + it * 256;          // 0..1023
            int row = u >> 3;                // 0..127
            int c16 = u & 7;                 // 16B unit within 128B row
            uint32_t off = row * 128 + c16 * 16;
            uint32_t sw = off ^ ((off >> 3) & 0x70);
            const __nv_bfloat16* pa  = &g_ah[(size_t)(brow + row) * KTOT + kcol + c16 * 8];
            const __nv_bfloat16* pal = &g_al[(size_t)(brow + row) * KTOT + kcol + c16 * 8];
            const __nv_bfloat16* pb  = &bh[(size_t)row * KTOT + kcol + c16 * 8];
            const __nv_bfloat16* pbl = &bl[(size_t)row * KTOT + kcol + c16 * 8];
            CP16(base + sw, pa);
            CP16(base + 16384 + sw, pal);
            CP16(base + 32768 + sw, pb);
            CP16(base + 49152 + sw, pbl);
        }
        asm volatile("cp.async.commit_group;" ::: "memory");
    };

    load_chunk(0, 0);

    for (int c = 0; c < NCHUNK; c++) {
        if (c + 1 < NCHUNK) {
            load_chunk(c + 1, (c + 1) & 1);
            asm volatile("cp.async.wait_group 1;" ::: "memory");
        } else {
            asm volatile("cp.async.wait_group 0;" ::: "memory");
        }
        __syncthreads();

        uint32_t base = smem_u + 1024 + (c & 1) * 65536;
#pragma unroll
        for (int ks = 0; ks < 4; ks++) {
            int kb = ks * 32 + kh16;   // byte offset of k within chunk row
            uint32_t ah[2][4], al[2][4], bhf[4][4], blf[4][4];
#pragma unroll
            for (int t = 0; t < 2; t++) {
                int row = wm * 32 + t * 16 + lrow;
                uint32_t off = row * 128 + kb;
                ldsm_x4(ah[t], base + (off ^ ((off >> 3) & 0x70)));
            }
#pragma unroll
            for (int p = 0; p < 4; p++) {
                int row = wn * 64 + p * 16 + lrow;
                uint32_t off = row * 128 + kb;
                ldsm_x4(bhf[p], base + 32768 + (off ^ ((off >> 3) & 0x70)));
            }
            // pass 0: Ah * Bh
#pragma unroll
            for (int t = 0; t < 2; t++)
#pragma unroll
                for (int p = 0; p < 4; p++) {
                    mma16816(acc[t][2 * p + 0], ah[t], bhf[p][0], bhf[p][2]);
                    mma16816(acc[t][2 * p + 1], ah[t], bhf[p][1], bhf[p][3]);
                }
            // pass 1: Al * Bh
#pragma unroll
            for (int t = 0; t < 2; t++) {
                int row = wm * 32 + t * 16 + lrow;
                uint32_t off = row * 128 + kb;
                ldsm_x4(al[t], base + 16384 + (off ^ ((off >> 3) & 0x70)));
            }
#pragma unroll
            for (int t = 0; t < 2; t++)
#pragma unroll
                for (int p = 0; p < 4; p++) {
                    mma16816(acc[t][2 * p + 0], al[t], bhf[p][0], bhf[p][2]);
                    mma16816(acc[t][2 * p + 1], al[t], bhf[p][1], bhf[p][3]);
                }
            // pass 2: Ah * Bl
#pragma unroll
            for (int p = 0; p < 4; p++) {
                int row = wn * 64 + p * 16 + lrow;
                uint32_t off = row * 128 + kb;
                ldsm_x4(blf[p], base + 49152 + (off ^ ((off >> 3) & 0x70)));
            }
#pragma unroll
            for (int t = 0; t < 2; t++)
#pragma unroll
                for (int p = 0; p < 4; p++) {
                    mma16816(acc[t][2 * p + 0], ah[t], blf[p][0], blf[p][2]);
                    mma16816(acc[t][2 * p + 1], ah[t], blf[p][1], blf[p][3]);
                }
        }
        __syncthreads();
    }

    // ---- stage acc + bias into smem (reuse tile area), stride 132 floats ----
    float* sOut = (float*)(smem + 1024);
#pragma unroll
    for (int t = 0; t < 2; t++) {
        int rr = wm * 32 + t * 16 + (lane >> 2);
#pragma unroll
        for (int q = 0; q < 8; q++) {
            int col = wn * 64 + (q >> 1) * 16 + (q & 1) * 8 + 2 * (lane & 3);
            float bx = sBias[col], by = sBias[col + 1];
            *reinterpret_cast<float2*>(&sOut[rr * 132 + col]) =
                make_float2(acc[t][q][0] + bx, acc[t][q][1] + by);
            *reinterpret_cast<float2*>(&sOut[(rr + 8) * 132 + col]) =
                make_float2(acc[t][q][2] + bx, acc[t][q][3] + by);
        }
    }
    __syncthreads();

    // ---- fused relu + residual + LayerNorm (+ next-layer bf16 self-cols) ----
    for (int rr = wid; rr < 128; rr += 8) {
        int row = brow + rr;
        if (row >= N_NODES) continue;
        float4 t = *reinterpret_cast<float4*>(&sOut[rr * 132 + lane * 4]);
        float4 xr = *reinterpret_cast<const float4*>(xin + (size_t)row * D + lane * 4);
        float4 v;
        v.x = fmaxf(t.x, 0.f) + xr.x;
        v.y = fmaxf(t.y, 0.f) + xr.y;
        v.z = fmaxf(t.z, 0.f) + xr.z;
        v.w = fmaxf(t.w, 0.f) + xr.w;
        float s = v.x + v.y + v.z + v.w;
        float sq = v.x * v.x + v.y * v.y + v.z * v.z + v.w * v.w;
#pragma unroll
        for (int o = 16; o; o >>= 1) {
            s += __shfl_xor_sync(0xFFFFFFFFu, s, o);
            sq += __shfl_xor_sync(0xFFFFFFFFu, sq, o);
        }
        float mean = s * (1.0f / 128.0f);
        float var = sq * (1.0f / 128.0f) - mean * mean;
        float rs = rsqrtf(var + 1e-5f);
        float4 g = *reinterpret_cast<const float4*>(gamma + lane * 4);
        float4 b = *reinterpret_cast<const float4*>(beta + lane * 4);
        float4 o;
        o.x = (v.x - mean) * rs * g.x + b.x;
        o.y = (v.y - mean) * rs * g.y + b.y;
        o.z = (v.z - mean) * rs * g.z + b.z;
        o.w = (v.w - mean) * rs * g.w + b.w;
        *reinterpret_cast<float4*>(xout + (size_t)row * D + lane * 4) = o;
        if (write_next) {
            float vv[4] = {o.x, o.y, o.z, o.w};
            __nv_bfloat16 h[4], lo[4];
#pragma unroll
            for (int j = 0; j < 4; j++) {
                h[j] = __float2bfloat16(vv[j]);
                lo[j] = __float2bfloat16(vv[j] - __bfloat162float(h[j]));
            }
            size_t oo = (size_t)row * KTOT + 512 + lane * 4;
            *reinterpret_cast<uint2*>(&g_ah[oo]) = *reinterpret_cast<uint2*>(h);
            *reinterpret_cast<uint2*>(&g_al[oo]) = *reinterpret_cast<uint2*>(lo);
        }
    }
}

// ---------------- host launcher ----------------
extern "C" void kernel_launch(void* const* d_in, const int* in_sizes, int n_in,
                              void* d_out, int out_size) {
    const float* x     = (const float*)d_in[0];
    const int*   ei    = (const int*)d_in[1];
    const int*   et    = (const int*)d_in[2];
    const float* W     = (const float*)d_in[3];
    const float* root  = (const float*)d_in[4];
    const float* bias  = (const float*)d_in[5];
    const float* gamma = (const float*)d_in[6];
    const float* beta  = (const float*)d_in[7];
    float* out = (float*)d_out;

    const int* src = ei;
    const int* dst = ei + N_EDGES;

    float *px1 = nullptr, *px2 = nullptr;
    cudaGetSymbolAddress((void**)&px1, g_x1);
    cudaGetSymbolAddress((void**)&px2, g_x2);

    cudaFuncSetAttribute(k_gemm, cudaFuncAttributeMaxDynamicSharedMemorySize, SMEM_DYN);

    // CSR build (edge structure is layer-invariant)
    k_zero_cnt<<<(NSEG + 255) / 256, 256>>>();
    k_hist<<<(N_EDGES + 255) / 256, 256>>>(dst, et);
    int nb = (NSEG + 1023) / 1024;
    k_scan1<<<nb, 1024>>>();
    k_scan23<<<nb, 1024>>>(nb);
    k_scatter<<<(N_EDGES + 255) / 256, 256>>>(src, dst, et);

    // weight transpose + split
    k_bprep<<<(NLAYER * D * KTOT + 255) / 256, 256>>>(W, root);
    // self-cols for layer 0
    k_convx<<<(N_NODES + 7) / 8, 256>>>(x);

    const float* xin = x;
    for (int l = 0; l < NLAYER; l++) {
        k_agg<<<(N_NODES + 7) / 8, 256>>>(xin);
        float* xout = (l == NLAYER - 1) ? out : ((l == 0) ? px1 : px2);
        k_gemm<<<NTILES, 256, SMEM_DYN>>>(l, bias + (size_t)l * D, xin,
                                          gamma + (size_t)l * D,
                                          beta + (size_t)l * D, xout,
                                          l < NLAYER - 1 ? 1 : 0);
        xin = xout;
    }
}